// round 4
// baseline (speedup 1.0000x reference)
#include <cuda_runtime.h>
#include <math.h>

// Problem constants
#define E_EDGES 100000
#define S_MEM   16
#define D_DIM   128
#define C_CLS   6
#define H_HEADS 4
#define M_IND   4
#define G_EDGES 8                       // edges per CTA
#define ROWS    (G_EDGES * S_MEM)       // 128 rows per CTA
#define NTHREADS 256

#define SCALE_INV_SQRT_DV 0.08838834764831845f  // 1/sqrt(128)

// Shared memory plan (floats):
//  bufA [128][128]  gathered V; later out = O + relu(O@Wo1)
//  bufB [128][128]  K0; later rows 96..127 = Hset, rows 0..31 = V1
//  bufC [128][128]  V0; later Q1; then O (attn1 out, in place)
//  sS1  [ 32][128]  O0; later K1
//  sW   [ 16][128]  staged weight k-tile
//  sScr [2048]      attention scores / staged Wout+bout
#define SMEM_FLOATS (3*ROWS*D_DIM + 32*D_DIM + 16*D_DIM + 2048)
#define SMEM_BYTES  (SMEM_FLOATS * 4)

__device__ __align__(16) float g_Iq[M_IND * D_DIM];  // I @ Wq0 + bq0

// -------- prolog: Iq = I @ Wq0 + bq0 --------
__global__ void iq_kernel(const float* __restrict__ I,
                          const float* __restrict__ Wq,
                          const float* __restrict__ bq) {
    int idx = blockIdx.x * blockDim.x + threadIdx.x;
    if (idx >= M_IND * D_DIM) return;
    int qi = idx / D_DIM, d = idx % D_DIM;
    float acc = bq[d];
#pragma unroll 8
    for (int k = 0; k < D_DIM; k++) acc += I[qi * D_DIM + k] * Wq[k * D_DIM + d];
    g_Iq[idx] = acc;
}

// -------- SMEM-tile GEMM: Y[MROWS][128] = X[MROWS][128] @ W[128][128] (+bias, epilogue) --------
template<int MROWS, bool SKIP_RELU>
__device__ __forceinline__ void gemm_tile(
    const float* __restrict__ Xs,          // smem [MROWS][128]
    const float* __restrict__ Wg,          // gmem [128][128]
    const float* __restrict__ bg,          // gmem [128]
    float* __restrict__ Ys,                // smem [MROWS][128]
    const float* __restrict__ Sk,          // smem skip (for SKIP_RELU)
    float* __restrict__ sW, int tid)
{
    constexpr int RPT = MROWS / 16;        // rows per thread
    const int tx = tid & 15;               // 16 col groups of 8
    const int ty = tid >> 4;               // 16 row groups of RPT

    float acc[RPT][8];
#pragma unroll
    for (int i = 0; i < RPT; i++)
#pragma unroll
        for (int j = 0; j < 8; j++) acc[i][j] = 0.f;

    float bias[8];
#pragma unroll
    for (int j = 0; j < 8; j++) bias[j] = bg[tx * 8 + j];

#pragma unroll 1
    for (int kt = 0; kt < 8; kt++) {
        __syncthreads();
        // stage W rows [kt*16, kt*16+16): 2048 floats, coalesced scalar loads
#pragma unroll
        for (int k = 0; k < 8; k++) {
            sW[tid + k * 256] = Wg[kt * 2048 + tid + k * 256];
        }
        __syncthreads();

#pragma unroll
        for (int kk = 0; kk < 16; kk += 4) {
            float a[RPT][4];
#pragma unroll
            for (int i = 0; i < RPT; i++) {
                float4 v = *reinterpret_cast<const float4*>(
                    &Xs[(ty * RPT + i) * D_DIM + kt * 16 + kk]);
                a[i][0] = v.x; a[i][1] = v.y; a[i][2] = v.z; a[i][3] = v.w;
            }
#pragma unroll
            for (int q = 0; q < 4; q++) {
                float4 b0 = *reinterpret_cast<const float4*>(&sW[(kk + q) * D_DIM + tx * 8]);
                float4 b1 = *reinterpret_cast<const float4*>(&sW[(kk + q) * D_DIM + tx * 8 + 4]);
                float bb[8] = {b0.x, b0.y, b0.z, b0.w, b1.x, b1.y, b1.z, b1.w};
#pragma unroll
                for (int i = 0; i < RPT; i++)
#pragma unroll
                    for (int j = 0; j < 8; j++) acc[i][j] += a[i][q] * bb[j];
            }
        }
    }

    // epilogue
#pragma unroll
    for (int i = 0; i < RPT; i++) {
        int row = ty * RPT + i;
        float o[8];
#pragma unroll
        for (int j = 0; j < 8; j++) {
            float v = acc[i][j] + bias[j];
            if (SKIP_RELU) v = Sk[row * D_DIM + tx * 8 + j] + fmaxf(v, 0.f);
            o[j] = v;
        }
        *reinterpret_cast<float4*>(&Ys[row * D_DIM + tx * 8])     = make_float4(o[0], o[1], o[2], o[3]);
        *reinterpret_cast<float4*>(&Ys[row * D_DIM + tx * 8 + 4]) = make_float4(o[4], o[5], o[6], o[7]);
    }
    __syncthreads();
}

// -------- main fused kernel: 8 edges per CTA --------
extern "C" __global__ void __launch_bounds__(NTHREADS)
whatsnet_kernel(const float* __restrict__ vfeat,
                const int*   __restrict__ member_idx,
                const int*   __restrict__ labels,
                const float* __restrict__ Wout, const float* __restrict__ bout,
                const float* __restrict__ Wk0,  const float* __restrict__ bk0,
                const float* __restrict__ Wv0,  const float* __restrict__ bv0,
                const float* __restrict__ Wo0,  const float* __restrict__ bo0,
                const float* __restrict__ Wq1,  const float* __restrict__ bq1,
                const float* __restrict__ Wk1,  const float* __restrict__ bk1,
                const float* __restrict__ Wv1,  const float* __restrict__ bv1,
                const float* __restrict__ Wo1,  const float* __restrict__ bo1,
                float* __restrict__ out,
                int n_nodes,
                long long out_capacity)
{
    extern __shared__ float smem[];
    float* bufA   = smem;
    float* bufB   = bufA + ROWS * D_DIM;
    float* bufC   = bufB + ROWS * D_DIM;
    float* sS1    = bufC + ROWS * D_DIM;   // 32*128
    float* sW     = sS1 + 32 * D_DIM;      // 16*128
    float* sScr   = sW + 16 * D_DIM;       // 2048

    const int tid = threadIdx.x;
    const int blk = blockIdx.x;
    const int rowbase = blk * ROWS;

    // ---- 1. gather vfeat[member_idx] -> bufA (clamped, coalesced) ----
    {
        int warp = tid >> 5, lane = tid & 31;
        for (int r = warp; r < ROWS; r += 8) {
            int n = member_idx[rowbase + r];
            if (n < 0) n = 0;
            if (n >= n_nodes) n = n_nodes - 1;
            const float* src = vfeat + (size_t)n * D_DIM;
#pragma unroll
            for (int k = 0; k < 4; k++)
                bufA[r * D_DIM + lane + k * 32] = src[lane + k * 32];
        }
    }
    __syncthreads();

    // ---- 2/3. K0 -> bufB ; V0 -> bufC ----
    gemm_tile<128, false>(bufA, Wk0, bk0, bufB, nullptr, sW, tid);
    gemm_tile<128, false>(bufA, Wv0, bv0, bufC, nullptr, sW, tid);

    // ---- 4. attention0: scores idx = ((e*4+h)*4+qi)*16 + s  (128 rows x 16) ----
#pragma unroll 1
    for (int it = 0; it < 8; it++) {
        int idx = tid + it * 256;
        int s  = idx & 15;
        int qi = (idx >> 4) & 3;
        int h  = (idx >> 6) & 3;
        int e  = idx >> 8;
        const float4* qv = reinterpret_cast<const float4*>(&g_Iq[qi * D_DIM + h * 32]);
        const float4* kv = reinterpret_cast<const float4*>(&bufB[(e * 16 + s) * D_DIM + h * 32]);
        float dot = 0.f;
#pragma unroll
        for (int d4 = 0; d4 < 8; d4++) {
            float4 q = qv[d4], k = kv[d4];
            dot += q.x * k.x + q.y * k.y + q.z * k.z + q.w * k.w;
        }
        sScr[idx] = dot * SCALE_INV_SQRT_DV;
    }
    __syncthreads();
    // softmax over s=16: 128 rows (e<8, h<4, qi<4)  [BUGFIX: was 512 -> SMEM OOB]
    if (tid < 128) {
        float* p = &sScr[tid * 16];
        float mx = p[0];
#pragma unroll
        for (int i = 1; i < 16; i++) mx = fmaxf(mx, p[i]);
        float sum = 0.f;
#pragma unroll
        for (int i = 0; i < 16; i++) { float ex = expf(p[i] - mx); p[i] = ex; sum += ex; }
        float inv = 1.f / sum;
#pragma unroll
        for (int i = 0; i < 16; i++) p[i] *= inv;
    }
    __syncthreads();
    // O0[e*4+qi][d] = Iq[qi][d] + sum_s A * V0  -> sS1 (32 rows)
#pragma unroll 1
    for (int it = 0; it < 16; it++) {
        int idx = tid + it * 256;          // row(32)*128 + d
        int d = idx & 127;
        int row = idx >> 7;
        int qi = row & 3, e = row >> 2;
        int h = d >> 5;
        float o = g_Iq[qi * D_DIM + d];
        const float* A  = &sScr[((e * 4 + h) * 4 + qi) * 16];
        const float* vv = &bufC[(e * 16) * D_DIM + d];
#pragma unroll
        for (int s = 0; s < 16; s++) o += A[s] * vv[s * D_DIM];
        sS1[idx] = o;
    }
    __syncthreads();

    // ---- 5. Hset = O0 + relu(O0@Wo0+bo0) -> bufB rows 96..127 ----
    gemm_tile<32, true>(sS1, Wo0, bo0, bufB + 96 * D_DIM, sS1, sW, tid);

    // ---- 6. Q1 = V@Wq1+bq1 -> bufC ----
    gemm_tile<128, false>(bufA, Wq1, bq1, bufC, nullptr, sW, tid);

    // ---- 7. K1 -> sS1 ; V1 -> bufB rows 0..31 ----
    gemm_tile<32, false>(bufB + 96 * D_DIM, Wk1, bk1, sS1, nullptr, sW, tid);
    gemm_tile<32, false>(bufB + 96 * D_DIM, Wv1, bv1, bufB, nullptr, sW, tid);

    // ---- 8. attention1: scores idx = ((e*4+h)*16+q)*4 + k  (512 rows x 4) ----
#pragma unroll 1
    for (int it = 0; it < 8; it++) {
        int idx = tid + it * 256;
        int k = idx & 3;
        int q = (idx >> 2) & 15;
        int h = (idx >> 6) & 3;
        int e = idx >> 8;
        const float4* qv = reinterpret_cast<const float4*>(&bufC[(e * 16 + q) * D_DIM + h * 32]);
        const float4* kv = reinterpret_cast<const float4*>(&sS1[(e * 4 + k) * D_DIM + h * 32]);
        float dot = 0.f;
#pragma unroll
        for (int d4 = 0; d4 < 8; d4++) {
            float4 qq = qv[d4], kk = kv[d4];
            dot += qq.x * kk.x + qq.y * kk.y + qq.z * kk.z + qq.w * kk.w;
        }
        sScr[idx] = dot * SCALE_INV_SQRT_DV;
    }
    __syncthreads();
    // softmax over k=4: 512 rows (e<8, h<4, q<16)
    for (int r = tid; r < 512; r += 256) {
        float* p = &sScr[r * 4];
        float mx = fmaxf(fmaxf(p[0], p[1]), fmaxf(p[2], p[3]));
        float e0 = expf(p[0] - mx), e1 = expf(p[1] - mx), e2 = expf(p[2] - mx), e3 = expf(p[3] - mx);
        float inv = 1.f / (e0 + e1 + e2 + e3);
        p[0] = e0 * inv; p[1] = e1 * inv; p[2] = e2 * inv; p[3] = e3 * inv;
    }
    __syncthreads();
    // O = Q1 + A1@V1, in place in bufC
#pragma unroll 1
    for (int it = 0; it < 64; it++) {
        int idx = tid + it * 256;          // row(128)*128 + d
        int d = idx & 127;
        int row = idx >> 7;
        int q = row & 15, e = row >> 4;
        int h = d >> 5;
        float o = bufC[idx];
        const float* A  = &sScr[((e * 4 + h) * 16 + q) * 4];
        const float* vv = &bufB[(e * 4) * D_DIM + d];
#pragma unroll
        for (int k = 0; k < 4; k++) o += A[k] * vv[k * D_DIM];
        bufC[idx] = o;
    }
    __syncthreads();

    // ---- 9. out = O + relu(O@Wo1+bo1) -> bufA ----
    gemm_tile<128, true>(bufC, Wo1, bo1, bufA, bufC, sW, tid);

    // ---- 10. logits = out@Wout + bout ----
    for (int i = tid; i < D_DIM * C_CLS; i += 256) sScr[i] = Wout[i];
    if (tid < C_CLS) sScr[D_DIM * C_CLS + tid] = bout[tid];
    __syncthreads();
#pragma unroll 1
    for (int it = 0; it < 3; it++) {
        int idx = tid + it * 256;          // r*6 + c
        int c = idx % C_CLS, r = idx / C_CLS;
        float acc = sScr[D_DIM * C_CLS + c];
        const float4* xr = reinterpret_cast<const float4*>(&bufA[r * D_DIM]);
#pragma unroll
        for (int k4 = 0; k4 < 32; k4++) {
            float4 x = xr[k4];
            acc += x.x * sScr[(k4 * 4 + 0) * C_CLS + c]
                 + x.y * sScr[(k4 * 4 + 1) * C_CLS + c]
                 + x.z * sScr[(k4 * 4 + 2) * C_CLS + c]
                 + x.w * sScr[(k4 * 4 + 3) * C_CLS + c];
        }
        long long off = (long long)(rowbase + r) * C_CLS + c;
        if (off < out_capacity) out[off] = acc;
    }

    // ---- 11. labels passthrough (only if the tuple fits) ----
    long long lab_base = (long long)E_EDGES * S_MEM * C_CLS;
    if (out_capacity >= lab_base + (long long)E_EDGES * S_MEM) {
        for (int r = tid; r < ROWS; r += 256) {
            out[lab_base + rowbase + r] = (float)labels[rowbase + r];
        }
    }
}

extern "C" void kernel_launch(void* const* d_in, const int* in_sizes, int n_in,
                              void* d_out, int out_size) {
    // --- size-based input identification (robust to slot permutation) ---
    const float* Ws[8] = {0,0,0,0,0,0,0,0};
    const float* Bs[8] = {0,0,0,0,0,0,0,0};
    const float* vfeat = 0; const float* Iin = 0;
    const float* Wout = 0;  const float* bout = 0;
    const int* member_idx = 0; const int* labels = 0;
    int wi = 0, bi = 0;
    int n_nodes = 500000;
    for (int i = 0; i < n_in; i++) {
        int sz = in_sizes[i];
        if (sz == 500000 * 128)      { vfeat = (const float*)d_in[i]; n_nodes = sz / D_DIM; }
        else if (sz == E_EDGES * S_MEM) {
            if (!member_idx) member_idx = (const int*)d_in[i];
            else if (!labels) labels = (const int*)d_in[i];
        }
        else if (sz == M_IND * D_DIM) Iin = (const float*)d_in[i];
        else if (sz == D_DIM * C_CLS) Wout = (const float*)d_in[i];
        else if (sz == C_CLS)         bout = (const float*)d_in[i];
        else if (sz == D_DIM * D_DIM) { if (wi < 8) Ws[wi++] = (const float*)d_in[i]; }
        else if (sz == D_DIM)         { if (bi < 8) Bs[bi++] = (const float*)d_in[i]; }
    }
    // fallback to positional order if anything is missing
    if (!vfeat || !member_idx || !labels || !Iin || !Wout || !bout || wi != 8 || bi != 8) {
        vfeat      = (const float*)d_in[0];
        member_idx = (const int*)  d_in[1];
        labels     = (const int*)  d_in[2];
        Iin        = (const float*)d_in[3];
        Wout       = (const float*)d_in[4];
        bout       = (const float*)d_in[5];
        for (int j = 0; j < 8; j++) {
            Ws[j] = (const float*)d_in[6 + 2 * j];
            Bs[j] = (const float*)d_in[7 + 2 * j];
        }
        n_nodes = in_sizes[0] / D_DIM;
    }
    // order within size class preserved: Wq0,Wk0,Wv0,Wo0,Wq1,Wk1,Wv1,Wo1
    const float *Wq0 = Ws[0], *Wk0 = Ws[1], *Wv0 = Ws[2], *Wo0 = Ws[3];
    const float *Wq1 = Ws[4], *Wk1 = Ws[5], *Wv1 = Ws[6], *Wo1 = Ws[7];
    const float *bq0 = Bs[0], *bk0 = Bs[1], *bv0 = Bs[2], *bo0 = Bs[3];
    const float *bq1 = Bs[4], *bk1 = Bs[5], *bv1 = Bs[6], *bo1 = Bs[7];

    float* out = (float*)d_out;

    cudaFuncSetAttribute(whatsnet_kernel, cudaFuncAttributeMaxDynamicSharedMemorySize, SMEM_BYTES);

    iq_kernel<<<2, 256>>>(Iin, Wq0, bq0);

    whatsnet_kernel<<<E_EDGES / G_EDGES, NTHREADS, SMEM_BYTES>>>(
        vfeat, member_idx, labels, Wout, bout,
        Wk0, bk0, Wv0, bv0, Wo0, bo0,
        Wq1, bq1, Wk1, bk1, Wv1, bv1, Wo1, bo1,
        out, n_nodes, (long long)out_size);
}